// round 3
// baseline (speedup 1.0000x reference)
#include <cuda_runtime.h>

#define NCO      513          // N_COEFFS
#define NPAIRS   256          // N_RES * EXPR
#define NFRAMES  128
#define STEP     512
#define FFTN     512          // complex FFT size (WINDOW/2)
#define HOPS     32
#define CHUNKS   (NFRAMES / HOPS)   // 4
#define PI_F     3.14159265358979323846f

// ---- persistent device scratch (no allocations allowed) ----
__device__ float  g_u[NPAIRS * NCO];    // (|amp|+eps)*cos(start_phase) / 1024
__device__ float  g_v[NPAIRS * NCO];    // (|amp|+eps)*sin(start_phase) / 1024
__device__ float  g_e[NPAIRS * NCO];    // signed decay: (k odd ? -d : d)
__device__ float2 g_win2[STEP];         // (win[2i], win[2i+1]) Hann pairs
__device__ float2 g_tw[256];            // e^{+2*pi*i*j/512}
__device__ float2 g_up[512];            // e^{+2*pi*i*k/1024} (irfft unpack)

// ---------------------------------------------------------------------------
// Table init (runs every launch; deterministic, negligible cost)
// ---------------------------------------------------------------------------
__global__ void init_tables_kernel() {
    int i = threadIdx.x;  // 0..511
    float s, c;
    sincospif(i * (1.0f / 512.0f), &s, &c);    // e^{+i*2*pi*i/1024}
    g_up[i] = make_float2(c, s);
    if (i < 256) {
        float s2, c2;
        sincospif(i * (1.0f / 256.0f), &s2, &c2);  // e^{+i*2*pi*i/512}
        g_tw[i] = make_float2(c2, s2);
    }
    // Hann: win[n] = 0.5 - 0.5*cos(2*pi*n/1024) = 0.5 - 0.5*cospi(n/512)
    float w0 = 0.5f - 0.5f * cospif((2 * i    ) * (1.0f / 512.0f));
    float w1 = 0.5f - 0.5f * cospif((2 * i + 1) * (1.0f / 512.0f));
    g_win2[i] = make_float2(w0, w1);
}

// ---------------------------------------------------------------------------
// Base spectrum precompute: transcendentals once per (pair,k), not per frame
// ---------------------------------------------------------------------------
__global__ void init_base_kernel(const float* __restrict__ amp,
                                 const float* __restrict__ phase,
                                 const float* __restrict__ decay) {
    int idx = blockIdx.x * 256 + threadIdx.x;
    if (idx >= 64 * NCO * 4) return;
    // input layout: [r][k][e], idx = (r*513 + k)*4 + e
    int e  = idx & 3;
    int rk = idx >> 2;
    int k  = rk % NCO;
    int r  = rk / NCO;

    float a  = amp[idx];
    float ph = phase[idx];
    float dc = decay[idx];

    float d  = 0.5f + 0.45f / (1.0f + expf(-dc));      // BASE_RES + sigmoid*span*factor
    float sp = tanhf(ph) * PI_F;                        // start phase
    float m0 = fabsf(a) + 1e-12f;                       // start mag + EPS
    float sn, cs;
    sincosf(sp, &sn, &cs);

    const float sc = 1.0f / 1024.0f;                    // fold irfft 1/N + packing /2
    int o = (r * 4 + e) * NCO + k;
    g_u[o] = m0 * cs * sc;
    g_v[o] = m0 * sn * sc;
    g_e[o] = (k & 1) ? -d : d;                          // folds (-1)^{f*k} sign flip
}

// ---------------------------------------------------------------------------
// Main fused kernel: spectrum -> 512-pt Stockham IFFT -> window -> overlap-add
// One block = one (pair, 32-hop chunk). 256 threads.
// ---------------------------------------------------------------------------
__global__ __launch_bounds__(256) void synth_kernel(float* __restrict__ out) {
    __shared__ float  su[NCO], sv[NCO], sw[NCO], se[NCO];
    __shared__ float2 bufA[FFTN], bufB[FFTN];
    __shared__ float2 carry[256];        // windowed 2nd half of previous frame
    __shared__ float2 swin[STEP];        // 512 pairs covering win[0..1023]
    __shared__ float2 stw[256];
    __shared__ float2 sup[512];

    const int t     = threadIdx.x;
    const int p     = blockIdx.x;        // pair
    const int chunk = blockIdx.y;
    const int h0    = chunk * HOPS;
    const int f0    = (chunk == 0) ? 0 : (h0 - 1);   // warm-up frame for carry

    const float* U = g_u + p * NCO;
    const float* V = g_v + p * NCO;
    const float* E = g_e + p * NCO;

    for (int k = t; k < NCO; k += 256) {
        su[k] = U[k];
        sv[k] = V[k];
        float e = E[k];
        se[k] = e;
        float d = fabsf(e);
        float w = expf((float)f0 * logf(d));           // d^{f0}
        if ((f0 & 1) && (k & 1)) w = -w;               // sign at starting frame
        sw[k] = w;
    }
    for (int i = t; i < STEP; i += 256) swin[i] = g_win2[i];
    stw[t] = g_tw[t];
    for (int i = t; i < 512; i += 256) sup[i] = g_up[i];
    if (chunk == 0) carry[t] = make_float2(0.0f, 0.0f);
    __syncthreads();

    float* outp = out + (size_t)p * 65536;

    const int fend = h0 + HOPS;
    for (int f = f0; f < fend; ++f) {
        // ---- build packed half-size spectrum Z[k] (natural order, coalesced) ----
        #pragma unroll
        for (int half = 0; half < 2; ++half) {
            int k = t + half * 256;
            float2 Zv;
            if (k == 0) {
                // bins 0 and 512: imaginary parts discarded by irfft convention
                float X0 = su[0]   * sw[0];
                float XM = su[512] * sw[512];
                Zv = make_float2(X0 + XM, X0 - XM);
            } else {
                int q = 512 - k;
                float wk = sw[k], wq = sw[q];
                float xr = su[k] * wk, xi = sv[k] * wk;
                float qr = su[q] * wq, qi = sv[q] * wq;
                float Ar = xr + qr, Ai = xi - qi;      // X[k] + conj(X[512-k])
                float Br = xr - qr, Bi = xi + qi;      // X[k] - conj(X[512-k])
                float2 tt = sup[k];                    // e^{+i*2*pi*k/1024}
                float tr = tt.x * Br - tt.y * Bi;
                float ti = tt.x * Bi + tt.y * Br;
                Zv = make_float2(Ar - ti, Ai + tr);    // Z = A + i*(t*B)
            }
            bufA[k] = Zv;
        }
        __syncthreads();

        // ---- 9-stage radix-2 Stockham inverse FFT (autosort, no bit-reversal) ----
        float2* src = bufA;
        float2* dst = bufB;
        #pragma unroll
        for (int st = 0; st < 9; ++st) {
            int s    = 1 << st;
            int twid = t & ~(s - 1);                   // p*s
            float2 w = stw[twid];
            float2 a = src[t];
            float2 b = src[t + 256];
            float2 apb = make_float2(a.x + b.x, a.y + b.y);
            float2 amb = make_float2(a.x - b.x, a.y - b.y);
            float2 wm  = make_float2(w.x * amb.x - w.y * amb.y,
                                     w.x * amb.y + w.y * amb.x);
            dst[t + twid]     = apb;
            dst[t + twid + s] = wm;
            __syncthreads();
            float2* tmp = src; src = dst; dst = tmp;
        }
        // result (natural order) now in src; z[n] = x[2n] + i*x[2n+1]

        // ---- window + overlap-add epilogue ----
        float2 zf  = src[t];          // x[2t], x[2t+1]         (first half)
        float2 zs  = src[t + 256];    // x[512+2t], x[513+2t]   (second half)
        float2 cin = carry[t];
        if (f >= h0) {
            float2 wv = swin[t];
            float2 o2 = make_float2(zf.x * wv.x + cin.x,
                                    zf.y * wv.y + cin.y);
            *(float2*)(outp + (size_t)f * STEP + 2 * t) = o2;
        }
        float2 wv2 = swin[256 + t];
        carry[t] = make_float2(zs.x * wv2.x, zs.y * wv2.y);

        // ---- advance magnitudes (sign-folded decay recurrence) ----
        for (int k = t; k < NCO; k += 256) sw[k] *= se[k];
        __syncthreads();
    }
}

// ---------------------------------------------------------------------------
extern "C" void kernel_launch(void* const* d_in, const int* in_sizes, int n_in,
                              void* d_out, int out_size) {
    const float* amp   = (const float*)d_in[0];
    const float* phase = (const float*)d_in[1];
    const float* decay = (const float*)d_in[2];
    float* out = (float*)d_out;

    init_tables_kernel<<<1, 512>>>();
    int total = 64 * NCO * 4;
    init_base_kernel<<<(total + 255) / 256, 256>>>(amp, phase, decay);

    dim3 grid(NPAIRS, CHUNKS);
    synth_kernel<<<grid, 256>>>(out);
}

// round 4
// speedup vs baseline: 1.0104x; 1.0104x over previous
#include <cuda_runtime.h>

#define NCO      513          // N_COEFFS
#define NPAIRS   256          // N_RES * EXPR
#define NFRAMES  128
#define STEP     512
#define FFTN     512          // complex FFT size (WINDOW/2)
#define HOPS     32
#define CHUNKS   (NFRAMES / HOPS)   // 4
#define PI_F     3.14159265358979323846f

// ---- persistent device scratch (no allocations allowed) ----
__device__ float  g_u[NPAIRS * NCO];    // (|amp|+eps)*cos(start_phase) / 1024
__device__ float  g_v[NPAIRS * NCO];    // (|amp|+eps)*sin(start_phase) / 1024
__device__ float  g_e[NPAIRS * NCO];    // signed decay: (k odd ? -d : d)
__device__ float2 g_win2[STEP];         // (win[2i], win[2i+1]) Hann pairs
__device__ float2 g_tw[256];            // e^{+2*pi*i*j/512}
__device__ float2 g_up[512];            // e^{+2*pi*i*k/1024} (irfft unpack)

// ---------------------------------------------------------------------------
// Table init (runs every launch; deterministic, negligible cost)
// ---------------------------------------------------------------------------
__global__ void init_tables_kernel() {
    int i = threadIdx.x;  // 0..511
    float s, c;
    sincospif(i * (1.0f / 512.0f), &s, &c);    // e^{+i*2*pi*i/1024}
    g_up[i] = make_float2(c, s);
    if (i < 256) {
        float s2, c2;
        sincospif(i * (1.0f / 256.0f), &s2, &c2);  // e^{+i*2*pi*i/512}
        g_tw[i] = make_float2(c2, s2);
    }
    // Hann: win[n] = 0.5 - 0.5*cos(2*pi*n/1024) = 0.5 - 0.5*cospi(n/512)
    float w0 = 0.5f - 0.5f * cospif((2 * i    ) * (1.0f / 512.0f));
    float w1 = 0.5f - 0.5f * cospif((2 * i + 1) * (1.0f / 512.0f));
    g_win2[i] = make_float2(w0, w1);
}

// ---------------------------------------------------------------------------
// Base spectrum precompute: transcendentals once per (pair,k), not per frame
// ---------------------------------------------------------------------------
__global__ void init_base_kernel(const float* __restrict__ amp,
                                 const float* __restrict__ phase,
                                 const float* __restrict__ decay) {
    int idx = blockIdx.x * 256 + threadIdx.x;
    if (idx >= 64 * NCO * 4) return;
    // input layout: [r][k][e], idx = (r*513 + k)*4 + e
    int e  = idx & 3;
    int rk = idx >> 2;
    int k  = rk % NCO;
    int r  = rk / NCO;

    float a  = amp[idx];
    float ph = phase[idx];
    float dc = decay[idx];

    float d  = 0.5f + 0.45f / (1.0f + expf(-dc));      // BASE_RES + sigmoid*span*factor
    float sp = tanhf(ph) * PI_F;                        // start phase
    float m0 = fabsf(a) + 1e-12f;                       // start mag + EPS
    float sn, cs;
    sincosf(sp, &sn, &cs);

    const float sc = 1.0f / 1024.0f;                    // fold irfft 1/N + packing /2
    int o = (r * 4 + e) * NCO + k;
    g_u[o] = m0 * cs * sc;
    g_v[o] = m0 * sn * sc;
    g_e[o] = (k & 1) ? -d : d;                          // folds (-1)^{f*k} sign flip
}

// ---------------------------------------------------------------------------
// Main fused kernel: spectrum -> 512-pt Stockham IFFT -> window -> overlap-add
// One block = one (pair, 32-hop chunk). 256 threads.
// ---------------------------------------------------------------------------
__global__ __launch_bounds__(256) void synth_kernel(float* __restrict__ out) {
    __shared__ float  su[NCO], sv[NCO], sw[NCO], se[NCO];
    __shared__ float2 bufA[FFTN], bufB[FFTN];
    __shared__ float2 carry[256];        // windowed 2nd half of previous frame
    __shared__ float2 swin[STEP];        // 512 pairs covering win[0..1023]
    __shared__ float2 stw[256];
    __shared__ float2 sup[512];

    const int t     = threadIdx.x;
    const int p     = blockIdx.x;        // pair
    const int chunk = blockIdx.y;
    const int h0    = chunk * HOPS;
    const int f0    = (chunk == 0) ? 0 : (h0 - 1);   // warm-up frame for carry

    const float* U = g_u + p * NCO;
    const float* V = g_v + p * NCO;
    const float* E = g_e + p * NCO;

    for (int k = t; k < NCO; k += 256) {
        su[k] = U[k];
        sv[k] = V[k];
        float e = E[k];
        se[k] = e;
        float d = fabsf(e);
        float w = expf((float)f0 * logf(d));           // d^{f0}
        if ((f0 & 1) && (k & 1)) w = -w;               // sign at starting frame
        sw[k] = w;
    }
    for (int i = t; i < STEP; i += 256) swin[i] = g_win2[i];
    stw[t] = g_tw[t];
    for (int i = t; i < 512; i += 256) sup[i] = g_up[i];
    if (chunk == 0) carry[t] = make_float2(0.0f, 0.0f);
    __syncthreads();

    float* outp = out + (size_t)p * 65536;

    const int fend = h0 + HOPS;
    for (int f = f0; f < fend; ++f) {
        // ---- build packed half-size spectrum Z[k] (natural order, coalesced) ----
        #pragma unroll
        for (int half = 0; half < 2; ++half) {
            int k = t + half * 256;
            float2 Zv;
            if (k == 0) {
                // bins 0 and 512: imaginary parts discarded by irfft convention
                float X0 = su[0]   * sw[0];
                float XM = su[512] * sw[512];
                Zv = make_float2(X0 + XM, X0 - XM);
            } else {
                int q = 512 - k;
                float wk = sw[k], wq = sw[q];
                float xr = su[k] * wk, xi = sv[k] * wk;
                float qr = su[q] * wq, qi = sv[q] * wq;
                float Ar = xr + qr, Ai = xi - qi;      // X[k] + conj(X[512-k])
                float Br = xr - qr, Bi = xi + qi;      // X[k] - conj(X[512-k])
                float2 tt = sup[k];                    // e^{+i*2*pi*k/1024}
                float tr = tt.x * Br - tt.y * Bi;
                float ti = tt.x * Bi + tt.y * Br;
                Zv = make_float2(Ar - ti, Ai + tr);    // Z = A + i*(t*B)
            }
            bufA[k] = Zv;
        }
        __syncthreads();

        // ---- 9-stage radix-2 Stockham inverse FFT (autosort, no bit-reversal) ----
        float2* src = bufA;
        float2* dst = bufB;
        #pragma unroll
        for (int st = 0; st < 9; ++st) {
            int s    = 1 << st;
            int twid = t & ~(s - 1);                   // p*s
            float2 w = stw[twid];
            float2 a = src[t];
            float2 b = src[t + 256];
            float2 apb = make_float2(a.x + b.x, a.y + b.y);
            float2 amb = make_float2(a.x - b.x, a.y - b.y);
            float2 wm  = make_float2(w.x * amb.x - w.y * amb.y,
                                     w.x * amb.y + w.y * amb.x);
            dst[t + twid]     = apb;
            dst[t + twid + s] = wm;
            __syncthreads();
            float2* tmp = src; src = dst; dst = tmp;
        }
        // result (natural order) now in src; z[n] = x[2n] + i*x[2n+1]

        // ---- window + overlap-add epilogue ----
        float2 zf  = src[t];          // x[2t], x[2t+1]         (first half)
        float2 zs  = src[t + 256];    // x[512+2t], x[513+2t]   (second half)
        float2 cin = carry[t];
        if (f >= h0) {
            float2 wv = swin[t];
            float2 o2 = make_float2(zf.x * wv.x + cin.x,
                                    zf.y * wv.y + cin.y);
            *(float2*)(outp + (size_t)f * STEP + 2 * t) = o2;
        }
        float2 wv2 = swin[256 + t];
        carry[t] = make_float2(zs.x * wv2.x, zs.y * wv2.y);

        // ---- advance magnitudes (sign-folded decay recurrence) ----
        for (int k = t; k < NCO; k += 256) sw[k] *= se[k];
        __syncthreads();
    }
}

// ---------------------------------------------------------------------------
extern "C" void kernel_launch(void* const* d_in, const int* in_sizes, int n_in,
                              void* d_out, int out_size) {
    const float* amp   = (const float*)d_in[0];
    const float* phase = (const float*)d_in[1];
    const float* decay = (const float*)d_in[2];
    float* out = (float*)d_out;

    init_tables_kernel<<<1, 512>>>();
    int total = 64 * NCO * 4;
    init_base_kernel<<<(total + 255) / 256, 256>>>(amp, phase, decay);

    dim3 grid(NPAIRS, CHUNKS);
    synth_kernel<<<grid, 256>>>(out);
}

// round 5
// speedup vs baseline: 2.4423x; 2.4172x over previous
#include <cuda_runtime.h>

#define NCO     513
#define NPAIRS  256
#define STEP    512
#define HOPS    32
#define CHUNKS  4
#define PI_F    3.14159265358979323846f

// ---- persistent device scratch ----
__device__ float  g_u[NPAIRS * NCO];     // (|amp|+eps)*cos(sp) / 1024
__device__ float  g_v[NPAIRS * NCO];     // (|amp|+eps)*sin(sp) / 1024
__device__ float  g_d[NPAIRS * NCO];     // decay magnitude d
__device__ float  g_d4[NPAIRS * NCO];    // d^4
__device__ float4 g_C[NPAIRS * 512];     // packed build coeffs (C1r,C1i,C2r,C2i)
__device__ float2 g_win2[512];           // Hann pairs (win[2n], win[2n+1])

// ---------------------------------------------------------------------------
__global__ void init_win_kernel() {
    int i = threadIdx.x;  // 0..511
    float w0 = 0.5f - 0.5f * cospif((2 * i    ) * (1.0f / 512.0f));
    float w1 = 0.5f - 0.5f * cospif((2 * i + 1) * (1.0f / 512.0f));
    g_win2[i] = make_float2(w0, w1);
}

__global__ void init_base_kernel(const float* __restrict__ amp,
                                 const float* __restrict__ phase,
                                 const float* __restrict__ decay) {
    int idx = blockIdx.x * 256 + threadIdx.x;
    if (idx >= 64 * NCO * 4) return;
    int e  = idx & 3;
    int rk = idx >> 2;
    int k  = rk % NCO;
    int r  = rk / NCO;

    float a  = amp[idx];
    float ph = phase[idx];
    float dc = decay[idx];

    float d  = 0.5f + 0.45f / (1.0f + expf(-dc));   // BASE_RES + sigmoid*span*factor
    float sp = tanhf(ph) * PI_F;
    float m0 = fabsf(a) + 1e-12f;
    float sn, cs;
    sincosf(sp, &sn, &cs);

    const float sc = 1.0f / 1024.0f;                // fold irfft 1/N + pack /2
    int o = (r * 4 + e) * NCO + k;
    g_u[o] = m0 * cs * sc;
    g_v[o] = m0 * sn * sc;
    g_d[o] = d;
    float d2 = d * d;
    g_d4[o] = d2 * d2;
}

// Z[k] = w[k]*C1[k] + w[512-k]*C2[k]  (irfft-unpack twiddle folded in)
__global__ void init_pack_kernel() {
    int idx = blockIdx.x * 256 + threadIdx.x;       // 256*512
    if (idx >= NPAIRS * 512) return;
    int k    = idx & 511;
    int pair = idx >> 9;
    const float* U = g_u + pair * NCO;
    const float* V = g_v + pair * NCO;
    float4 c;
    if (k == 0) {
        c = make_float4(U[0], U[0], U[512], -U[512]);   // imag parts dropped
    } else {
        int q = 512 - k;
        float ty, tx;
        sincospif(k * (1.0f / 512.0f), &ty, &tx);   // e^{+2pi i k/1024}
        float suk = U[k], svk = V[k], suq = U[q], svq = V[q];
        c.x =  suk * (1.0f - ty) - tx * svk;
        c.y =  svk * (1.0f - ty) + tx * suk;
        c.z =  suq * (1.0f + ty) - tx * svq;
        c.w = -svq * (1.0f + ty) - tx * suq;
    }
    g_C[idx] = c;
}

// ---------------------------------------------------------------------------
__device__ __forceinline__ float2 cmul(float2 a, float2 b) {
    return make_float2(a.x * b.x - a.y * b.y, a.x * b.y + a.y * b.x);
}
__device__ __forceinline__ float2 cadd(float2 a, float2 b) {
    return make_float2(a.x + b.x, a.y + b.y);
}
__device__ __forceinline__ float2 csub(float2 a, float2 b) {
    return make_float2(a.x - b.x, a.y - b.y);
}

// natural-order inverse DFT-8 (kernel e^{+2pi i j r/8}) on registers
__device__ __forceinline__ void fft8(float2* a) {
    const float RH = 0.70710678118654752440f;
    float2 t0 = cadd(a[0], a[4]), t1 = csub(a[0], a[4]);
    float2 t2 = cadd(a[2], a[6]), t3 = csub(a[2], a[6]);
    float2 E0 = cadd(t0, t2), E2 = csub(t0, t2);
    float2 E1 = make_float2(t1.x - t3.y, t1.y + t3.x);
    float2 E3 = make_float2(t1.x + t3.y, t1.y - t3.x);
    float2 s0 = cadd(a[1], a[5]), s1 = csub(a[1], a[5]);
    float2 s2 = cadd(a[3], a[7]), s3 = csub(a[3], a[7]);
    float2 O0 = cadd(s0, s2), O2 = csub(s0, s2);
    float2 O1 = make_float2(s1.x - s3.y, s1.y + s3.x);
    float2 O3 = make_float2(s1.x + s3.y, s1.y - s3.x);
    float2 W1 = make_float2((O1.x - O1.y) * RH, (O1.x + O1.y) * RH);
    float2 W2 = make_float2(-O2.y, O2.x);
    float2 W3 = make_float2(-(O3.x + O3.y) * RH, (O3.x - O3.y) * RH);
    a[0] = cadd(E0, O0);  a[4] = csub(E0, O0);
    a[1] = cadd(E1, W1);  a[5] = csub(E1, W1);
    a[2] = cadd(E2, W2);  a[6] = csub(E2, W2);
    a[3] = cadd(E3, W3);  a[7] = csub(E3, W3);
}

__device__ __forceinline__ void gbar(int g) {
    asm volatile("bar.sync %0, %1;" :: "r"(g + 1), "r"(64) : "memory");
}

// ---------------------------------------------------------------------------
// One block = (pair, 32-hop chunk); 4 groups x 64 threads, 4 frames / iter.
// Radix-8 Stockham (s = 1, 8, 64) register-resident, 2 smem exchanges.
// ---------------------------------------------------------------------------
__global__ __launch_bounds__(256, 2) void synth_kernel(float* __restrict__ out) {
    __shared__ float  e4s[NCO];        // d^4 per bin
    __shared__ float  xre[4][528];     // exchange buffer (re), padded
    __shared__ float  xim[4][528];     // exchange buffer (im)
    __shared__ float2 cring[6][256];   // overlap-add carry ring
    __shared__ float2 winp[512];       // Hann pairs

    const int tid   = threadIdx.x;
    const int g     = tid >> 6;        // frame group 0..3
    const int t     = tid & 63;        // lane within group
    const int pair  = blockIdx.x;
    const int chunk = blockIdx.y;
    const int h0    = chunk * HOPS;
    const int f0    = chunk ? (h0 - 1) : 0;
    const int fmax  = h0 + HOPS - 1;
    const int NIT   = chunk ? 9 : 8;

    for (int i = tid; i < NCO; i += 256) e4s[i] = g_d4[pair * NCO + i];
    for (int i = tid; i < 512; i += 256) winp[i] = g_win2[i];
    cring[0][tid] = make_float2(0.0f, 0.0f);
    __syncthreads();

    // ---- per-thread persistent state ----
    float4 C[8];
    float  wk[8], wq[8];
    float2 tws1[8], tws2[8];
    {
        const int   fs  = f0 + g;
        const float fsf = (float)fs;
        #pragma unroll
        for (int r = 0; r < 8; ++r) {
            int k = t + 64 * r;
            int q = 512 - k;
            C[r] = g_C[pair * 512 + k];
            float dk = g_d[pair * NCO + k];
            float dq = g_d[pair * NCO + q];
            float a = exp2f(fsf * log2f(dk));               // d^fs
            float b = exp2f(fsf * log2f(dq));
            if ((fs & 1) && (k & 1)) { a = -a; b = -b; }    // (-1)^{fs*k}
            wk[r] = a; wq[r] = b;
        }
        int p2 = t >> 3;
        #pragma unroll
        for (int j = 1; j < 8; ++j) {
            float s, c;
            sincospif((float)(j * t) * (1.0f / 256.0f), &s, &c);   // e^{2pi i jt/512}
            tws1[j] = make_float2(c, s);
            float s2, c2;
            sincospif((float)(j * p2) * (1.0f / 32.0f), &s2, &c2); // e^{2pi i j(t>>3)/64}
            tws2[j] = make_float2(c2, s2);
        }
    }

    float* myre = xre[g];
    float* myim = xim[g];
    float* outp = out + (size_t)pair * 65536;

    for (int it = 0; it < NIT; ++it) {
        const int  frame = f0 + 4 * it + g;
        const bool valid = (frame <= fmax);
        float2 a[8];

        if (valid) {
            // ---- build spectrum in registers ----
            #pragma unroll
            for (int r = 0; r < 8; ++r) {
                a[r].x = wk[r] * C[r].x + wq[r] * C[r].z;
                a[r].y = wk[r] * C[r].y + wq[r] * C[r].w;
            }

            // ---- stage 1 (s=1) ----
            fft8(a);
            #pragma unroll
            for (int j = 1; j < 8; ++j) a[j] = cmul(a[j], tws1[j]);
            #pragma unroll
            for (int j = 0; j < 8; ++j) {            // write x = 8t+j, pad32
                int x = 8 * t + j; int px = x + (x >> 5);
                myre[px] = a[j].x; myim[px] = a[j].y;
            }
            gbar(g);
            #pragma unroll
            for (int r = 0; r < 8; ++r) {            // read x = t+64r
                int x = t + 64 * r; int px = x + (x >> 5);
                a[r] = make_float2(myre[px], myim[px]);
            }

            // ---- stage 2 (s=8) ----
            fft8(a);
            #pragma unroll
            for (int j = 1; j < 8; ++j) a[j] = cmul(a[j], tws2[j]);
            gbar(g);                                 // WAR: stage-1 reads done
            #pragma unroll
            for (int j = 0; j < 8; ++j) {            // write x = q+64p+8j, xor swizzle
                int x = (t & 7) + 64 * (t >> 3) + 8 * j;
                int sx = x ^ ((x >> 3) & 0x18);
                myre[sx] = a[j].x; myim[sx] = a[j].y;
            }
            gbar(g);
            #pragma unroll
            for (int r = 0; r < 8; ++r) {            // read x = t+64r
                int x = t + 64 * r;
                int sx = x ^ ((x >> 3) & 0x18);
                a[r] = make_float2(myre[sx], myim[sx]);
            }

            // ---- stage 3 (s=64): z[t+64j] in registers ----
            fft8(a);

            // ---- carry: windowed second half (j=4..7 -> n in [256,512)) ----
            int wslot = (4 * it + g + 1) % 6;
            #pragma unroll
            for (int j = 4; j < 8; ++j) {
                int n = t + 64 * j;
                float2 wv = winp[n];
                cring[wslot][n - 256] = make_float2(a[j].x * wv.x, a[j].y * wv.y);
            }
        }
        __syncthreads();

        if (valid && frame >= h0) {
            int rslot = (4 * it + g) % 6;
            #pragma unroll
            for (int j = 0; j < 4; ++j) {
                int n = t + 64 * j;
                float2 wv = winp[n];
                float2 cv = cring[rslot][n];
                float2 o;
                o.x = a[j].x * wv.x + cv.x;
                o.y = a[j].y * wv.y + cv.y;
                *(float2*)(outp + (size_t)frame * STEP + 2 * n) = o;
            }
        }
        __syncthreads();

        // ---- advance decay by d^4 (sign invariant under f -> f+4) ----
        #pragma unroll
        for (int r = 0; r < 8; ++r) {
            int k = t + 64 * r;
            wk[r] *= e4s[k];
            wq[r] *= e4s[512 - k];
        }
    }
}

// ---------------------------------------------------------------------------
extern "C" void kernel_launch(void* const* d_in, const int* in_sizes, int n_in,
                              void* d_out, int out_size) {
    const float* amp   = (const float*)d_in[0];
    const float* phase = (const float*)d_in[1];
    const float* decay = (const float*)d_in[2];
    float* out = (float*)d_out;

    init_win_kernel<<<1, 512>>>();
    int total = 64 * NCO * 4;
    init_base_kernel<<<(total + 255) / 256, 256>>>(amp, phase, decay);
    init_pack_kernel<<<(NPAIRS * 512 + 255) / 256, 256>>>();

    dim3 grid(NPAIRS, CHUNKS);
    synth_kernel<<<grid, 256>>>(out);
}